// round 12
// baseline (speedup 1.0000x reference)
#include <cuda_runtime.h>
#include <cuda_fp16.h>
#include <cstdint>

#define N_DIM 512

// ---------------- scratch ----------------
__device__ __half g_Bh[128 * 512];             // fp16 W: rows 0..63 = Ws, 64..127 = Wo
__device__ __half g_P[(size_t)100000 * 128];   // fp16 P (25.6MB): [0..63]=s, [64..127]=o
__device__ int    g_ticket;                    // dynamic tile ticket (reset by prep each launch)

// ---------------- smem geometry (3-stage, M=128, K-chunk=32) ----------------
#define A_STAGE_B 16384                        // 128 rows x 128B fp32, XOR-swizzled, no pad
#define B_ROW_H   48                           // 32 data halfs + 16 pad (conflict-free LDS.64)
#define B_STAGE_B (128 * B_ROW_H * 2)          // 12288
#define B_OFF     (3 * A_STAGE_B)              // 49152
#define SMEM_BYTES (3 * A_STAGE_B + 3 * B_STAGE_B) // 86016

// ---------------- helpers ----------------
__device__ __forceinline__ void cp16(uint32_t saddr, const void* g) {
    asm volatile("cp.async.cg.shared.global [%0], [%1], 16;" :: "r"(saddr), "l"(g));
}
__device__ __forceinline__ void cp_commit() {
    asm volatile("cp.async.commit_group;" ::: "memory");
}
template <int N>
__device__ __forceinline__ void cp_wait() {
    asm volatile("cp.async.wait_group %0;" :: "n"(N) : "memory");
}
__device__ __forceinline__ uint32_t smem_u32(const void* p) {
    uint32_t a;
    asm("{ .reg .u64 t; cvta.to.shared.u64 t, %1; cvt.u32.u64 %0, t; }" : "=r"(a) : "l"(p));
    return a;
}
__device__ __forceinline__ void hmma16816(float d[4], const uint32_t a[4], uint32_t b0, uint32_t b1) {
    asm volatile("mma.sync.aligned.m16n8k16.row.col.f32.f16.f16.f32 "
                 "{%0,%1,%2,%3},{%4,%5,%6,%7},{%8,%9},{%0,%1,%2,%3};"
                 : "+f"(d[0]), "+f"(d[1]), "+f"(d[2]), "+f"(d[3])
                 : "r"(a[0]), "r"(a[1]), "r"(a[2]), "r"(a[3]), "r"(b0), "r"(b1));
}
__device__ __forceinline__ uint32_t pack_h2(float x, float y) {
    __half2 h = __floats2half2_rn(x, y);
    return *reinterpret_cast<uint32_t*>(&h);
}
// A swizzle: within 128B row r, 16B-granule byte col c -> c ^ (((r&1)<<6)|((r&6)<<3))
__device__ __forceinline__ uint32_t axor(int row) {
    return ((row & 1) << 6) | ((row & 6) << 3);
}

// ---------------- kernel 0: W fp32 -> fp16 reorder + ticket reset ----------------
__global__ __launch_bounds__(128) void prep_kernel(const float* __restrict__ W, int grid0) {
    if (blockIdx.x == 0 && threadIdx.x == 0) g_ticket = grid0;
    int i = (blockIdx.x * 128 + threadIdx.x) * 2;
    if (i >= 128 * 512) return;
    int n = i >> 9, k = i & 511;
    const float* src = (n < 64) ? (W + n * 1024 + k) : (W + (n - 64) * 1024 + 512 + k);
    float2 v = *(const float2*)src;
    *(__half2*)&g_Bh[i] = __floats2half2_rn(v.x, v.y);
}

// ---------------- kernel 1: P = emb @ B^T, dynamic tiles, 2 CTA/SM, 3-stage K=32 ----------------
__global__ __launch_bounds__(256, 2) void gemm_kernel(const float* __restrict__ emb,
                                                      int n_nodes, int ntiles) {
    extern __shared__ char smem[];
    const uint32_t sb = smem_u32(smem);
    const int tid = threadIdx.x;
    const int lane = tid & 31;
    const int wid = tid >> 5;
    const int wm = wid & 3;     // 4 M-tiles of 32 (CTA M=128)
    const int wn = wid >> 2;    // 2 N-tiles of 64

    __shared__ int s_nxt;

    // producer: (tile, kchunk c, stage)
    auto ISSUE = [&](int tile, int c, int st) {
        if (tile >= ntiles) return;
        const int ctaM = tile * 128;
        const uint32_t aBase = sb + st * A_STAGE_B;
        const uint32_t bBase = sb + B_OFF + st * B_STAGE_B;
        #pragma unroll
        for (int i = 0; i < 4; i++) {           // A: 1024 granules of 16B
            int gr = tid + i * 256;
            int row = gr >> 3, col = gr & 7;
            int ar = ctaM + row;
            if (ar >= n_nodes) ar = n_nodes - 1;
            cp16(aBase + row * 128 + (((uint32_t)col * 16) ^ axor(row)),
                 emb + (size_t)ar * N_DIM + c * 32 + col * 4);
        }
        #pragma unroll
        for (int i = 0; i < 2; i++) {           // B: 512 granules (L2-resident g_Bh)
            int gr = tid + i * 256;
            int row = gr >> 2, col = gr & 3;
            cp16(bBase + row * (B_ROW_H * 2) + col * 16,
                 g_Bh + row * N_DIM + c * 32 + col * 8);
        }
    };

    float acc[2][8][4];
    #pragma unroll
    for (int i = 0; i < 2; i++)
        #pragma unroll
        for (int j = 0; j < 8; j++)
            #pragma unroll
            for (int k = 0; k < 4; k++) acc[i][j][k] = 0.0f;

    int cur = blockIdx.x;
    int nxt = -1;

    ISSUE(cur, 0, 0); cp_commit();
    ISSUE(cur, 1, 1); cp_commit();

    const int q = lane & 3;
    const int octr = lane >> 2;
    const uint32_t axm = axor(octr);   // consumed rows satisfy r0 & 7 == octr

    for (int g = 0; ; g++) {
        const int local = g & 15;
        if (local == 0) {
            if (cur >= ntiles) break;
            if (tid == 0) s_nxt = atomicAdd(&g_ticket, 1);
        }
        // pending entering wait: {g, g+1} -> wait<1> forces chunk g complete
        cp_wait<1>();
        __syncthreads();           // stage-g visible; all warps done with g-1 -> stage (g+2)%3 free
        if (local == 0) nxt = s_nxt;

        {   // refill stream position g+2 (tile = cur unless it crosses the 16-chunk boundary)
            const int gi = g + 2;
            const int itile = ((gi >> 4) == (g >> 4)) ? cur : nxt;
            ISSUE(itile, gi & 15, gi % 3);
            cp_commit();           // unconditional: keeps positional group count
        }

        const uint32_t aOff = (g % 3) * A_STAGE_B;
        const uint32_t bOff = B_OFF + (g % 3) * B_STAGE_B;

        #pragma unroll
        for (int ks = 0; ks < 2; ks++) {
            uint32_t afr[2][4];
            #pragma unroll
            for (int mt = 0; mt < 2; mt++) {
                const int r0 = wm * 32 + mt * 16 + octr;
                const uint32_t cx = ((uint32_t)(ks * 64 + q * 16)) ^ axm;
                const float4 v0 = *(const float4*)(smem + aOff + r0 * 128 + cx);
                const float4 v1 = *(const float4*)(smem + aOff + (r0 + 8) * 128 + cx);
                afr[mt][0] = pack_h2(v0.x, v0.y);
                afr[mt][1] = pack_h2(v1.x, v1.y);
                afr[mt][2] = pack_h2(v0.z, v0.w);
                afr[mt][3] = pack_h2(v1.z, v1.w);
            }
            uint2 bfr[8];
            #pragma unroll
            for (int nf = 0; nf < 8; nf++) {
                const int n = wn * 64 + nf * 8 + octr;
                bfr[nf] = *(const uint2*)(smem + bOff + n * (B_ROW_H * 2) + ks * 32 + q * 8);
            }
            #pragma unroll
            for (int mt = 0; mt < 2; mt++)
                #pragma unroll
                for (int nf = 0; nf < 8; nf++)
                    hmma16816(acc[mt][nf], afr[mt], bfr[nf].x, bfr[nf].y);
        }

        if (local == 15) {
            // epilogue for cur (next tile's chunks already in flight)
            const int ctaM = cur * 128;
            #pragma unroll
            for (int mt = 0; mt < 2; mt++) {
                const int r0 = ctaM + wm * 32 + mt * 16 + (lane >> 2);
                const int r1 = r0 + 8;
                #pragma unroll
                for (int nf = 0; nf < 8; nf++) {
                    const int col = wn * 64 + nf * 8 + (lane & 3) * 2;
                    if (r0 < n_nodes)
                        *(uint32_t*)&g_P[(size_t)r0 * 128 + col] = pack_h2(acc[mt][nf][0], acc[mt][nf][1]);
                    if (r1 < n_nodes)
                        *(uint32_t*)&g_P[(size_t)r1 * 128 + col] = pack_h2(acc[mt][nf][2], acc[mt][nf][3]);
                    acc[mt][nf][0] = acc[mt][nf][1] = acc[mt][nf][2] = acc[mt][nf][3] = 0.0f;
                }
            }
            cur = nxt;
        }
    }
    cp_wait<0>();   // drain any guarded/garbage groups before exit
}

// ---------------- kernel 2: per-triple gather-combine, 2 triples/thread, fp16 P ----------------
__global__ __launch_bounds__(256) void gather_kernel(const int* __restrict__ triples,
                                                     const float* __restrict__ b,
                                                     float* __restrict__ out, int n) {
    int t = blockIdx.x * blockDim.x + threadIdx.x;
    int half = (n + 1) >> 1;
    if (t >= half) return;
    int t2 = t + half;
    bool has2 = t2 < n;

    int s1 = triples[t],  r1 = triples[n + t],  o1 = triples[2 * n + t];
    int s2 = 0, r2 = 0, o2 = 0;
    if (has2) { s2 = triples[t2]; r2 = triples[n + t2]; o2 = triples[2 * n + t2]; }

    __half a1 = __ldg(&g_P[(size_t)s1 * 128 + r1]);
    __half c1 = __ldg(&g_P[(size_t)o1 * 128 + 64 + r1]);
    __half a2 = __float2half(0.f), c2 = __float2half(0.f);
    if (has2) {
        a2 = __ldg(&g_P[(size_t)s2 * 128 + r2]);
        c2 = __ldg(&g_P[(size_t)o2 * 128 + 64 + r2]);
    }

    out[t] = __half2float(a1) + __half2float(c1) + __ldg(&b[r1]);
    if (has2) out[t2] = __half2float(a2) + __half2float(c2) + __ldg(&b[r2]);
}

extern "C" void kernel_launch(void* const* d_in, const int* in_sizes, int n_in,
                              void* d_out, int out_size)
{
    const float* emb     = (const float*)d_in[0];
    const float* W       = (const float*)d_in[1];
    const float* b       = (const float*)d_in[2];
    const int*   triples = (const int*)d_in[3];
    float*       out     = (float*)d_out;

    int n_nodes = in_sizes[0] / N_DIM;   // 100000
    int n_tr    = in_sizes[3] / 3;       // 200000
    int ntiles  = (n_nodes + 127) / 128; // 782

    static int nsm = 0;
    if (nsm == 0) {
        cudaDeviceGetAttribute(&nsm, cudaDevAttrMultiProcessorCount, 0);
        cudaFuncSetAttribute(gemm_kernel, cudaFuncAttributeMaxDynamicSharedMemorySize, SMEM_BYTES);
    }
    int grid = 2 * nsm;
    if (grid > ntiles) grid = ntiles;

    prep_kernel<<<256, 128>>>(W, grid);
    gemm_kernel<<<grid, 256, SMEM_BYTES>>>(emb, n_nodes, ntiles);
    gather_kernel<<<((n_tr + 1) / 2 + 255) / 256, 256>>>(triples, b, out, n_tr);
}